// round 1
// baseline (speedup 1.0000x reference)
#include <cuda_runtime.h>
#include <math.h>

#define Bq    8
#define Sq    512
#define Dm    768
#define Hh    12
#define Dk    64
#define BHn   (Bq*Hh)            // 96
#define Mrows (Bq*Sq)            // 4096
#define NATT  (25165824)         // B*H*S*S
#define SCALE 0.036084391824351615f   // 1/sqrt(768)

// Scratch (device globals: allocation-free, graph-capturable)
__device__ float  g_proj[6u * Mrows * Dm];       // [6][4096][768]  ql,kl,qr,kr,q,k
__device__ float  g_softmask[(size_t)BHn * Sq * Sq];  // [B,H,S,S]
__device__ double g_loss;

// ---------------------------------------------------------------------------
// GEMM: C = (A @ W + bias) * scale ; A [4096,768], W [768,768]
// 128x128 tile, K-chunk 8, 8x8 micro per thread, 256 threads
// ---------------------------------------------------------------------------
__global__ __launch_bounds__(256) void gemm128(
    const float* __restrict__ A, const float* __restrict__ W,
    const float* __restrict__ bias, int wout, float scale)
{
    __shared__ float As[8][128];   // transposed A chunk: [k][m]
    __shared__ float Ws[8][128];   // [k][n]
    float* C = g_proj + (size_t)wout * Mrows * Dm;

    int tid = threadIdx.x;
    int m0 = blockIdx.x * 128;
    int n0 = blockIdx.y * 128;
    int ty = tid >> 4, tx = tid & 15;
    int arow = tid >> 1, ac4 = (tid & 1) * 4;
    int wrow = tid >> 5, wc4 = (tid & 31) * 4;

    float acc[8][8];
#pragma unroll
    for (int r = 0; r < 8; r++)
#pragma unroll
        for (int c = 0; c < 8; c++) acc[r][c] = 0.0f;

    for (int kk = 0; kk < Dm; kk += 8) {
        float4 av = *(const float4*)&A[(size_t)(m0 + arow) * Dm + kk + ac4];
        float4 wv = *(const float4*)&W[(size_t)(kk + wrow) * Dm + n0 + wc4];
        __syncthreads();
        As[ac4 + 0][arow] = av.x; As[ac4 + 1][arow] = av.y;
        As[ac4 + 2][arow] = av.z; As[ac4 + 3][arow] = av.w;
        *(float4*)&Ws[wrow][wc4] = wv;
        __syncthreads();
#pragma unroll
        for (int i = 0; i < 8; i++) {
            float4 a0 = *(const float4*)&As[i][ty * 8];
            float4 a1 = *(const float4*)&As[i][ty * 8 + 4];
            float4 b0 = *(const float4*)&Ws[i][tx * 8];
            float4 b1 = *(const float4*)&Ws[i][tx * 8 + 4];
            float av8[8] = {a0.x, a0.y, a0.z, a0.w, a1.x, a1.y, a1.z, a1.w};
            float bv8[8] = {b0.x, b0.y, b0.z, b0.w, b1.x, b1.y, b1.z, b1.w};
#pragma unroll
            for (int r = 0; r < 8; r++)
#pragma unroll
                for (int c = 0; c < 8; c++) acc[r][c] += av8[r] * bv8[c];
        }
    }

    float4 bb0 = *(const float4*)&bias[n0 + tx * 8];
    float4 bb1 = *(const float4*)&bias[n0 + tx * 8 + 4];
    float bv[8] = {bb0.x, bb0.y, bb0.z, bb0.w, bb1.x, bb1.y, bb1.z, bb1.w};
#pragma unroll
    for (int r = 0; r < 8; r++) {
        size_t base = (size_t)(m0 + ty * 8 + r) * Dm + n0 + tx * 8;
        float4 o0, o1;
        o0.x = (acc[r][0] + bv[0]) * scale;
        o0.y = (acc[r][1] + bv[1]) * scale;
        o0.z = (acc[r][2] + bv[2]) * scale;
        o0.w = (acc[r][3] + bv[3]) * scale;
        o1.x = (acc[r][4] + bv[4]) * scale;
        o1.y = (acc[r][5] + bv[5]) * scale;
        o1.z = (acc[r][6] + bv[6]) * scale;
        o1.w = (acc[r][7] + bv[7]) * scale;
        *(float4*)&C[base]     = o0;
        *(float4*)&C[base + 4] = o1;
    }
}

// ---------------------------------------------------------------------------
// Attention: per-(bh, 16-q-row tile) block, 256 threads.
// mode 0: left branch  -> softmax(scores - (k>q ? 1e9 : 0)), cumsum -> g_softmask
// mode 1: right branch -> softmax(scores - (k<q ? 1e9 : 0)), rev-cumsum, *= g_softmask
// mode 2: main         -> softmax((scores - rmq - rmk) * softmask) -> out, + BCE
// ---------------------------------------------------------------------------
__global__ __launch_bounds__(256) void attn_kernel(
    int mode, const float* __restrict__ mask,
    const float* __restrict__ span, float* __restrict__ out)
{
    __shared__ float sQ[16][64];
    __shared__ float sKT[16][512];
    __shared__ float sRed[16][2];
    __shared__ float sW[8];

    int tid  = threadIdx.x;
    int lane = tid & 31;
    int half = (tid >> 5) & 1;
    int qg   = tid >> 6;     // 0..3 -> q-group (4 rows each)
    int kg   = tid & 63;     // 0..63 -> 8 consecutive cols each
    int bh = blockIdx.y;
    int b = bh / Hh, h = bh % Hh;
    int q0 = blockIdx.x * 16;

    const float* Ap = g_proj + (size_t)(mode * 2)     * Mrows * Dm;
    const float* Bp = g_proj + (size_t)(mode * 2 + 1) * Mrows * Dm;

    {
        int row = tid >> 4;
        int d4  = (tid & 15) * 4;
        *(float4*)&sQ[row][d4] =
            *(const float4*)&Ap[((size_t)(b * Sq + q0 + row)) * Dm + h * Dk + d4];
    }

    float acc[4][8];
#pragma unroll
    for (int r = 0; r < 4; r++)
#pragma unroll
        for (int c = 0; c < 8; c++) acc[r][c] = 0.0f;

    for (int dc = 0; dc < 4; dc++) {
        __syncthreads();
#pragma unroll
        for (int i = 0; i < 8; i++) {
            int lin = i * 256 + tid;
            int tok = lin >> 2;
            int f4  = (lin & 3) * 4;
            float4 v = *(const float4*)&Bp[((size_t)(b * Sq + tok)) * Dm + h * Dk + dc * 16 + f4];
            sKT[f4 + 0][tok] = v.x; sKT[f4 + 1][tok] = v.y;
            sKT[f4 + 2][tok] = v.z; sKT[f4 + 3][tok] = v.w;
        }
        __syncthreads();
#pragma unroll
        for (int dd = 0; dd < 16; dd++) {
            float4 k0 = *(const float4*)&sKT[dd][kg * 8];
            float4 k1 = *(const float4*)&sKT[dd][kg * 8 + 4];
#pragma unroll
            for (int r = 0; r < 4; r++) {
                float qv = sQ[qg * 4 + r][dc * 16 + dd];
                acc[r][0] += qv * k0.x; acc[r][1] += qv * k0.y;
                acc[r][2] += qv * k0.z; acc[r][3] += qv * k0.w;
                acc[r][4] += qv * k1.x; acc[r][5] += qv * k1.y;
                acc[r][6] += qv * k1.z; acc[r][7] += qv * k1.w;
            }
        }
    }
    __syncthreads();

    float rmk[8], rmq[4];
    if (mode == 2) {
#pragma unroll
        for (int c = 0; c < 8; c++) {
            float mv = mask[b * Sq + kg * 8 + c];
            rmk[c] = (mv == -10000.0f) ? 1.0e9f : mv;
        }
#pragma unroll
        for (int r = 0; r < 4; r++) {
            float mv = mask[b * Sq + q0 + qg * 4 + r];
            rmq[r] = (mv == -10000.0f) ? 1.0e9f : mv;
        }
    }

    // transform + per-row max
#pragma unroll
    for (int r = 0; r < 4; r++) {
        int q = q0 + qg * 4 + r;
        if (mode == 0) {
#pragma unroll
            for (int c = 0; c < 8; c++)
                if (kg * 8 + c > q) acc[r][c] -= 1.0e9f;
        } else if (mode == 1) {
#pragma unroll
            for (int c = 0; c < 8; c++)
                if (kg * 8 + c < q) acc[r][c] -= 1.0e9f;
        } else {
            size_t idx = ((size_t)bh * Sq + q) * Sq + kg * 8;
            float4 s0 = *(const float4*)&g_softmask[idx];
            float4 s1 = *(const float4*)&g_softmask[idx + 4];
            float sm[8] = {s0.x, s0.y, s0.z, s0.w, s1.x, s1.y, s1.z, s1.w};
#pragma unroll
            for (int c = 0; c < 8; c++)
                acc[r][c] = (acc[r][c] - rmq[r] - rmk[c]) * sm[c];
        }
        float m = acc[r][0];
#pragma unroll
        for (int c = 1; c < 8; c++) m = fmaxf(m, acc[r][c]);
#pragma unroll
        for (int off = 16; off >= 1; off >>= 1)
            m = fmaxf(m, __shfl_xor_sync(0xffffffffu, m, off));
        if (lane == 0) sRed[qg * 4 + r][half] = m;
    }
    __syncthreads();
    float mrow[4];
#pragma unroll
    for (int r = 0; r < 4; r++)
        mrow[r] = fmaxf(sRed[qg * 4 + r][0], sRed[qg * 4 + r][1]);
    __syncthreads();

    if (mode < 2) {
        float tval[4];
#pragma unroll
        for (int r = 0; r < 4; r++) {
            float run = 0.0f;
#pragma unroll
            for (int c = 0; c < 8; c++) {
                run += __expf(acc[r][c] - mrow[r]);
                acc[r][c] = run;                 // local inclusive cumsum
            }
            float t = run;
#pragma unroll
            for (int off = 1; off < 32; off <<= 1) {
                float u = __shfl_up_sync(0xffffffffu, t, off);
                if (lane >= off) t += u;
            }
            tval[r] = t;                          // inclusive total within warp
            if (lane == 31) sRed[qg * 4 + r][half] = t;
        }
        __syncthreads();
#pragma unroll
        for (int r = 0; r < 4; r++) {
            int q = q0 + qg * 4 + r;
            float w0 = sRed[qg * 4 + r][0], w1 = sRed[qg * 4 + r][1];
            float sumrow = w0 + w1;
            float tot = acc[r][7];
            float excl = (half ? w0 : 0.0f) + (tval[r] - tot);
            float inv = 1.0f / sumrow;
            size_t idx = ((size_t)bh * Sq + q) * Sq + kg * 8;
            if (mode == 0) {
                float4 o0, o1;
                o0.x = (excl + acc[r][0]) * inv; o0.y = (excl + acc[r][1]) * inv;
                o0.z = (excl + acc[r][2]) * inv; o0.w = (excl + acc[r][3]) * inv;
                o1.x = (excl + acc[r][4]) * inv; o1.y = (excl + acc[r][5]) * inv;
                o1.z = (excl + acc[r][6]) * inv; o1.w = (excl + acc[r][7]) * inv;
                *(float4*)&g_softmask[idx]     = o0;
                *(float4*)&g_softmask[idx + 4] = o1;
            } else {
                // rev_incl[c] = sumrow - excl - local_incl[c-1]
                float4 s0 = *(const float4*)&g_softmask[idx];
                float4 s1 = *(const float4*)&g_softmask[idx + 4];
                float base = sumrow - excl;
                s0.x *= base * inv;
                s0.y *= (base - acc[r][0]) * inv;
                s0.z *= (base - acc[r][1]) * inv;
                s0.w *= (base - acc[r][2]) * inv;
                s1.x *= (base - acc[r][3]) * inv;
                s1.y *= (base - acc[r][4]) * inv;
                s1.z *= (base - acc[r][5]) * inv;
                s1.w *= (base - acc[r][6]) * inv;
                *(float4*)&g_softmask[idx]     = s0;
                *(float4*)&g_softmask[idx + 4] = s1;
            }
        }
    } else {
        float lsum = 0.0f;
#pragma unroll
        for (int r = 0; r < 4; r++) {
            float s = 0.0f;
#pragma unroll
            for (int c = 0; c < 8; c++) {
                acc[r][c] = __expf(acc[r][c] - mrow[r]);
                s += acc[r][c];
            }
#pragma unroll
            for (int off = 16; off >= 1; off >>= 1)
                s += __shfl_xor_sync(0xffffffffu, s, off);
            if (lane == 0) sRed[qg * 4 + r][half] = s;
        }
        __syncthreads();
#pragma unroll
        for (int r = 0; r < 4; r++) {
            int q = q0 + qg * 4 + r;
            float inv = 1.0f / (sRed[qg * 4 + r][0] + sRed[qg * 4 + r][1]);
            size_t oidx = ((size_t)bh * Sq + q) * Sq + kg * 8;
            size_t sidx = ((size_t)((h * Bq + b) * Sq + q)) * Sq + kg * 8;
            float4 sp0 = *(const float4*)&span[sidx];
            float4 sp1 = *(const float4*)&span[sidx + 4];
            float sp[8] = {sp0.x, sp0.y, sp0.z, sp0.w, sp1.x, sp1.y, sp1.z, sp1.w};
            float p[8];
#pragma unroll
            for (int c = 0; c < 8; c++) p[c] = acc[r][c] * inv;
            float4 o0 = {p[0], p[1], p[2], p[3]};
            float4 o1 = {p[4], p[5], p[6], p[7]};
            *(float4*)&out[oidx]     = o0;
            *(float4*)&out[oidx + 4] = o1;
#pragma unroll
            for (int c = 0; c < 8; c++)
                lsum += __logf(1.0f + __expf(-p[c])) + p[c] * (1.0f - sp[c]);
        }
#pragma unroll
        for (int off = 16; off >= 1; off >>= 1)
            lsum += __shfl_xor_sync(0xffffffffu, lsum, off);
        __syncthreads();
        if (lane == 0) sW[tid >> 5] = lsum;
        __syncthreads();
        if (tid == 0) {
            float tot = 0.0f;
#pragma unroll
            for (int w = 0; w < 8; w++) tot += sW[w];
            atomicAdd(&g_loss, (double)tot);
        }
    }
}

__global__ void zero_loss_kernel() { g_loss = 0.0; }

__global__ void finalize_kernel(float* out, int out_size) {
    if (out_size > NATT)
        out[NATT] = (float)(g_loss / (double)NATT);
}

// ---------------------------------------------------------------------------
extern "C" void kernel_launch(void* const* d_in, const int* in_sizes, int n_in,
                              void* d_out, int out_size)
{
    (void)in_sizes; (void)n_in;
    const float* query = (const float*)d_in[0];
    const float* key   = (const float*)d_in[1];
    const float* mask  = (const float*)d_in[2];
    const float* span  = (const float*)d_in[3];
    float* out = (float*)d_out;

    dim3 gg(Mrows / 128, Dm / 128);
    for (int w = 0; w < 6; w++) {
        const float* A    = (w & 1) ? key : query;       // 0 ql,1 kl,2 qr,3 kr,4 q,5 k
        const float* W    = (const float*)d_in[4 + 2 * w];
        const float* bias = (const float*)d_in[5 + 2 * w];
        float scale = (w & 1) ? 1.0f : SCALE;
        gemm128<<<gg, 256>>>(A, W, bias, w, scale);
    }
    zero_loss_kernel<<<1, 1>>>();

    dim3 ag(Sq / 16, BHn);
    attn_kernel<<<ag, 256>>>(0, mask, span, out);   // left  -> softmask = cumsum(theta_l)
    attn_kernel<<<ag, 256>>>(1, mask, span, out);   // right -> softmask *= revcumsum(theta_r)
    attn_kernel<<<ag, 256>>>(2, mask, span, out);   // main  -> p_local_attn + BCE
    finalize_kernel<<<1, 1>>>(out, out_size);
}

// round 3
// speedup vs baseline: 1.4066x; 1.4066x over previous
#include <cuda_runtime.h>
#include <cstdint>
#include <math.h>

#define Bq    8
#define Sq    512
#define Dm    768
#define Hh    12
#define Dk    64
#define BHn   (Bq*Hh)            // 96
#define Mrows (Bq*Sq)            // 4096
#define NATT  (25165824)         // B*H*S*S
#define SCALE 0.036084391824351615f   // 1/sqrt(768)

// ---- mma.sync tf32 GEMM tiling ----
#define BM 128
#define BN 64
#define BK 32
#define ASTR 36                        // padded k-stride (floats), conflict-free
#define A_BYTES (BM*ASTR*4)            // 18432
#define B_BYTES (BN*ASTR*4)            // 9216
#define STAGE_B (A_BYTES + B_BYTES)    // 27648
#define DYN_SMEM (2*STAGE_B)           // 55296
#define NSTAGE (Dm/BK)                 // 24

// Scratch (device globals: allocation-free, graph-capturable)
__device__ float  g_proj[(size_t)6 * Mrows * Dm];   // ql,kl,qr,kr,q,k
__device__ float  g_wT[(size_t)6 * Dm * Dm];        // W transposed: wT[n][k]
__device__ double g_loss;

struct Ptr6 { const float* p[6]; };

// ---------------------------------------------------------------------------
// helpers
// ---------------------------------------------------------------------------
__device__ __forceinline__ uint32_t smem_u32(const void* p) {
    uint32_t a;
    asm("{ .reg .u64 t; cvta.to.shared.u64 t, %1; cvt.u32.u64 %0, t; }"
        : "=r"(a) : "l"(p));
    return a;
}
__device__ __forceinline__ void cp16(uint32_t s, const void* g) {
    asm volatile("cp.async.ca.shared.global [%0], [%1], 16;"
                 :: "r"(s), "l"(g) : "memory");
}
__device__ __forceinline__ void cp_commit() {
    asm volatile("cp.async.commit_group;" ::: "memory");
}
template <int N>
__device__ __forceinline__ void cp_wait() {
    asm volatile("cp.async.wait_group %0;" :: "n"(N) : "memory");
}
__device__ __forceinline__ void split_tf32(float a, uint32_t& hi, uint32_t& lo) {
    uint32_t h;
    asm("cvt.rna.tf32.f32 %0, %1;" : "=r"(h) : "f"(a));
    float r = a - __uint_as_float(h);
    uint32_t l;
    asm("cvt.rna.tf32.f32 %0, %1;" : "=r"(l) : "f"(r));
    hi = h; lo = l;
}
__device__ __forceinline__ void mma8(float* c, const uint32_t* a, const uint32_t* b) {
    asm volatile(
        "mma.sync.aligned.m16n8k8.row.col.f32.tf32.tf32.f32 "
        "{%0,%1,%2,%3}, {%4,%5,%6,%7}, {%8,%9}, {%0,%1,%2,%3};"
        : "+f"(c[0]), "+f"(c[1]), "+f"(c[2]), "+f"(c[3])
        : "r"(a[0]), "r"(a[1]), "r"(a[2]), "r"(a[3]), "r"(b[0]), "r"(b[1]));
}

// ---------------------------------------------------------------------------
// Transpose all 6 weight matrices: g_wT[w][n][k] = W[w][k][n]
// ---------------------------------------------------------------------------
__global__ void transpose6(Ptr6 ws) {
    __shared__ float t[32][33];
    int w = blockIdx.z;
    const float* W = ws.p[w];
    float* T = g_wT + (size_t)w * Dm * Dm;
    int n0 = blockIdx.x * 32, k0 = blockIdx.y * 32;
#pragma unroll
    for (int i = 0; i < 4; i++)
        t[threadIdx.y + i * 8][threadIdx.x] =
            W[(size_t)(k0 + threadIdx.y + i * 8) * Dm + n0 + threadIdx.x];
    __syncthreads();
#pragma unroll
    for (int i = 0; i < 4; i++)
        T[(size_t)(n0 + threadIdx.y + i * 8) * Dm + k0 + threadIdx.x] =
            t[threadIdx.x][threadIdx.y + i * 8];
}

// ---------------------------------------------------------------------------
// mma.sync tf32 GEMM (3x split): C = (A @ W + bias) * scale
// grid (32 m, 12 n, 6 gemms), 256 threads, cp.async double-buffered
// ---------------------------------------------------------------------------
__global__ __launch_bounds__(256, 2) void gemm_mma(const float* __restrict__ query,
                                                   const float* __restrict__ key,
                                                   Ptr6 biases)
{
    extern __shared__ char dsm[];
    const int tid = threadIdx.x, warp = tid >> 5, lane = tid & 31;
    const int g = lane >> 2, t = lane & 3;
    const int wm = (warp >> 1) * 32, wn = (warp & 1) * 32;

    const int w = blockIdx.z;
    const float* A  = (w & 1) ? key : query;
    const float* Wt = g_wT + (size_t)w * Dm * Dm;
    float* C        = g_proj + (size_t)w * Mrows * Dm;
    const float* bias = biases.p[w];
    const float scale = (w & 1) ? 1.0f : SCALE;
    const int m0 = blockIdx.x * BM, n0 = blockIdx.y * BN;

    const uint32_t sb = smem_u32(dsm);

    auto load_stage = [&](int s, int buf) {
        const int kk = s * BK;
        const uint32_t ab = sb + buf * STAGE_B;
        const uint32_t bb = ab + A_BYTES;
#pragma unroll
        for (int i = 0; i < 4; i++) {          // A: 128x32 floats
            int li = i * 256 + tid;
            int row = li >> 3, kq = (li & 7) * 4;
            cp16(ab + (uint32_t)(row * ASTR + kq) * 4,
                 &A[(size_t)(m0 + row) * Dm + kk + kq]);
        }
#pragma unroll
        for (int i = 0; i < 2; i++) {          // B: 64x32 floats
            int li = i * 256 + tid;
            int row = li >> 3, kq = (li & 7) * 4;
            cp16(bb + (uint32_t)(row * ASTR + kq) * 4,
                 &Wt[(size_t)(n0 + row) * Dm + kk + kq]);
        }
        cp_commit();
    };

    float acc[2][4][4];
#pragma unroll
    for (int mf = 0; mf < 2; mf++)
#pragma unroll
        for (int nf = 0; nf < 4; nf++)
#pragma unroll
            for (int i = 0; i < 4; i++) acc[mf][nf][i] = 0.0f;

    load_stage(0, 0);

    for (int s = 0; s < NSTAGE; s++) {
        if (s + 1 < NSTAGE) { load_stage(s + 1, (s + 1) & 1); cp_wait<1>(); }
        else                { cp_wait<0>(); }
        __syncthreads();

        const int buf = s & 1;
        const float* As = (const float*)(dsm + buf * STAGE_B);
        const float* Bs = (const float*)(dsm + buf * STAGE_B + A_BYTES);

#pragma unroll
        for (int ks = 0; ks < 4; ks++) {
            const int kq = ks * 8;
            uint32_t ah[2][4], al[2][4], bh[4][2], bl[4][2];
#pragma unroll
            for (int mf = 0; mf < 2; mf++) {
                int r0 = wm + mf * 16 + g;
                split_tf32(As[r0 * ASTR + kq + t],           ah[mf][0], al[mf][0]);
                split_tf32(As[(r0 + 8) * ASTR + kq + t],     ah[mf][1], al[mf][1]);
                split_tf32(As[r0 * ASTR + kq + t + 4],       ah[mf][2], al[mf][2]);
                split_tf32(As[(r0 + 8) * ASTR + kq + t + 4], ah[mf][3], al[mf][3]);
            }
#pragma unroll
            for (int nf = 0; nf < 4; nf++) {
                int n = wn + nf * 8 + g;
                split_tf32(Bs[n * ASTR + kq + t],     bh[nf][0], bl[nf][0]);
                split_tf32(Bs[n * ASTR + kq + t + 4], bh[nf][1], bl[nf][1]);
            }
#pragma unroll
            for (int mf = 0; mf < 2; mf++)
#pragma unroll
                for (int nf = 0; nf < 4; nf++) {
                    mma8(acc[mf][nf], ah[mf], bh[nf]);
                    mma8(acc[mf][nf], ah[mf], bl[nf]);
                    mma8(acc[mf][nf], al[mf], bh[nf]);
                }
        }
        __syncthreads();
    }

    // Epilogue: c frag rows {g, g+8}, cols {2t, 2t+1} within each m16n8 tile
#pragma unroll
    for (int mf = 0; mf < 2; mf++) {
        int row0 = m0 + wm + mf * 16 + g;
#pragma unroll
        for (int nf = 0; nf < 4; nf++) {
            int col = n0 + wn + nf * 8 + 2 * t;
            float2 bv = *(const float2*)&bias[col];
            float2 o0, o1;
            o0.x = (acc[mf][nf][0] + bv.x) * scale;
            o0.y = (acc[mf][nf][1] + bv.y) * scale;
            o1.x = (acc[mf][nf][2] + bv.x) * scale;
            o1.y = (acc[mf][nf][3] + bv.y) * scale;
            *(float2*)&C[(size_t)row0 * Dm + col]       = o0;
            *(float2*)&C[(size_t)(row0 + 8) * Dm + col] = o1;
        }
    }
}

// ---------------------------------------------------------------------------
// Fused attention: per-(bh, 16-q-row tile) block, 256 threads.
// All three branches in one kernel; softmask lives in registers (smk[4][8]).
// ---------------------------------------------------------------------------
__global__ __launch_bounds__(256) void attn_fused(
    const float* __restrict__ mask,
    const float* __restrict__ span, float* __restrict__ out)
{
    __shared__ float sQ[16][64];
    __shared__ float sKT[16][512];
    __shared__ float sRed[16][2];
    __shared__ float sW[8];

    int tid  = threadIdx.x;
    int lane = tid & 31;
    int half = (tid >> 5) & 1;
    int qg   = tid >> 6;     // 0..3 -> q-group (4 rows each)
    int kg   = tid & 63;     // 0..63 -> 8 consecutive cols each
    int bh = blockIdx.y;
    int b = bh / Hh, h = bh % Hh;
    int q0 = blockIdx.x * 16;

    float smk[4][8];     // running soft mask (cumsum products), per-thread

    float rmk[8], rmq[4];
#pragma unroll
    for (int c = 0; c < 8; c++) {
        float mv = mask[b * Sq + kg * 8 + c];
        rmk[c] = (mv == -10000.0f) ? 1.0e9f : mv;
    }
#pragma unroll
    for (int r = 0; r < 4; r++) {
        float mv = mask[b * Sq + q0 + qg * 4 + r];
        rmq[r] = (mv == -10000.0f) ? 1.0e9f : mv;
    }

    for (int mode = 0; mode < 3; mode++) {
        const float* Ap = g_proj + (size_t)(mode * 2)     * Mrows * Dm;
        const float* Bp = g_proj + (size_t)(mode * 2 + 1) * Mrows * Dm;

        __syncthreads();
        {
            int row = tid >> 4;
            int d4  = (tid & 15) * 4;
            *(float4*)&sQ[row][d4] =
                *(const float4*)&Ap[((size_t)(b * Sq + q0 + row)) * Dm + h * Dk + d4];
        }

        float acc[4][8];
#pragma unroll
        for (int r = 0; r < 4; r++)
#pragma unroll
            for (int c = 0; c < 8; c++) acc[r][c] = 0.0f;

        for (int dc = 0; dc < 4; dc++) {
            __syncthreads();
#pragma unroll
            for (int i = 0; i < 8; i++) {
                int lin = i * 256 + tid;
                int tok = lin >> 2;
                int f4  = (lin & 3) * 4;
                float4 v = *(const float4*)&Bp[((size_t)(b * Sq + tok)) * Dm + h * Dk + dc * 16 + f4];
                sKT[f4 + 0][tok] = v.x; sKT[f4 + 1][tok] = v.y;
                sKT[f4 + 2][tok] = v.z; sKT[f4 + 3][tok] = v.w;
            }
            __syncthreads();
#pragma unroll
            for (int dd = 0; dd < 16; dd++) {
                float4 k0 = *(const float4*)&sKT[dd][kg * 8];
                float4 k1 = *(const float4*)&sKT[dd][kg * 8 + 4];
#pragma unroll
                for (int r = 0; r < 4; r++) {
                    float qv = sQ[qg * 4 + r][dc * 16 + dd];
                    acc[r][0] += qv * k0.x; acc[r][1] += qv * k0.y;
                    acc[r][2] += qv * k0.z; acc[r][3] += qv * k0.w;
                    acc[r][4] += qv * k1.x; acc[r][5] += qv * k1.y;
                    acc[r][6] += qv * k1.z; acc[r][7] += qv * k1.w;
                }
            }
        }
        __syncthreads();

        // transform + per-row max
#pragma unroll
        for (int r = 0; r < 4; r++) {
            int q = q0 + qg * 4 + r;
            if (mode == 0) {
#pragma unroll
                for (int c = 0; c < 8; c++)
                    if (kg * 8 + c > q) acc[r][c] -= 1.0e9f;
            } else if (mode == 1) {
#pragma unroll
                for (int c = 0; c < 8; c++)
                    if (kg * 8 + c < q) acc[r][c] -= 1.0e9f;
            } else {
#pragma unroll
                for (int c = 0; c < 8; c++)
                    acc[r][c] = (acc[r][c] - rmq[r] - rmk[c]) * smk[r][c];
            }
            float m = acc[r][0];
#pragma unroll
            for (int c = 1; c < 8; c++) m = fmaxf(m, acc[r][c]);
#pragma unroll
            for (int off = 16; off >= 1; off >>= 1)
                m = fmaxf(m, __shfl_xor_sync(0xffffffffu, m, off));
            if (lane == 0) sRed[qg * 4 + r][half] = m;
        }
        __syncthreads();
        float mrow[4];
#pragma unroll
        for (int r = 0; r < 4; r++)
            mrow[r] = fmaxf(sRed[qg * 4 + r][0], sRed[qg * 4 + r][1]);
        __syncthreads();

        if (mode < 2) {
            float tval[4];
#pragma unroll
            for (int r = 0; r < 4; r++) {
                float run = 0.0f;
#pragma unroll
                for (int c = 0; c < 8; c++) {
                    run += __expf(acc[r][c] - mrow[r]);
                    acc[r][c] = run;                 // local inclusive cumsum
                }
                float tv = run;
#pragma unroll
                for (int off = 1; off < 32; off <<= 1) {
                    float u = __shfl_up_sync(0xffffffffu, tv, off);
                    if (lane >= off) tv += u;
                }
                tval[r] = tv;                         // inclusive total within warp
                if (lane == 31) sRed[qg * 4 + r][half] = tv;
            }
            __syncthreads();
#pragma unroll
            for (int r = 0; r < 4; r++) {
                float w0 = sRed[qg * 4 + r][0], w1 = sRed[qg * 4 + r][1];
                float sumrow = w0 + w1;
                float tot = acc[r][7];
                float excl = (half ? w0 : 0.0f) + (tval[r] - tot);
                float inv = 1.0f / sumrow;
                if (mode == 0) {
#pragma unroll
                    for (int c = 0; c < 8; c++)
                        smk[r][c] = (excl + acc[r][c]) * inv;
                } else {
                    // rev_incl[c] = sumrow - excl - local_incl[c-1]
                    float base = sumrow - excl;
                    smk[r][0] *= base * inv;
#pragma unroll
                    for (int c = 1; c < 8; c++)
                        smk[r][c] *= (base - acc[r][c - 1]) * inv;
                }
            }
        } else {
            float lsum = 0.0f;
#pragma unroll
            for (int r = 0; r < 4; r++) {
                float s = 0.0f;
#pragma unroll
                for (int c = 0; c < 8; c++) {
                    acc[r][c] = __expf(acc[r][c] - mrow[r]);
                    s += acc[r][c];
                }
#pragma unroll
                for (int off = 16; off >= 1; off >>= 1)
                    s += __shfl_xor_sync(0xffffffffu, s, off);
                if (lane == 0) sRed[qg * 4 + r][half] = s;
            }
            __syncthreads();
#pragma unroll
            for (int r = 0; r < 4; r++) {
                int q = q0 + qg * 4 + r;
                float inv = 1.0f / (sRed[qg * 4 + r][0] + sRed[qg * 4 + r][1]);
                size_t oidx = ((size_t)bh * Sq + q) * Sq + kg * 8;
                size_t sidx = ((size_t)((h * Bq + b) * Sq + q)) * Sq + kg * 8;
                float4 sp0 = *(const float4*)&span[sidx];
                float4 sp1 = *(const float4*)&span[sidx + 4];
                float sp[8] = {sp0.x, sp0.y, sp0.z, sp0.w, sp1.x, sp1.y, sp1.z, sp1.w};
                float p[8];
#pragma unroll
                for (int c = 0; c < 8; c++) p[c] = acc[r][c] * inv;
                float4 o0 = {p[0], p[1], p[2], p[3]};
                float4 o1 = {p[4], p[5], p[6], p[7]};
                *(float4*)&out[oidx]     = o0;
                *(float4*)&out[oidx + 4] = o1;
#pragma unroll
                for (int c = 0; c < 8; c++)
                    lsum += __logf(1.0f + __expf(-p[c])) + p[c] * (1.0f - sp[c]);
            }
#pragma unroll
            for (int off = 16; off >= 1; off >>= 1)
                lsum += __shfl_xor_sync(0xffffffffu, lsum, off);
            __syncthreads();
            if (lane == 0) sW[tid >> 5] = lsum;
            __syncthreads();
            if (tid == 0) {
                float tot = 0.0f;
#pragma unroll
                for (int ww = 0; ww < 8; ww++) tot += sW[ww];
                atomicAdd(&g_loss, (double)tot);
            }
        }
    }
}

__global__ void zero_loss_kernel() { g_loss = 0.0; }

__global__ void finalize_kernel(float* out, int out_size) {
    if (out_size > NATT)
        out[NATT] = (float)(g_loss / (double)NATT);
}

// ---------------------------------------------------------------------------
extern "C" void kernel_launch(void* const* d_in, const int* in_sizes, int n_in,
                              void* d_out, int out_size)
{
    (void)in_sizes; (void)n_in;
    const float* query = (const float*)d_in[0];
    const float* key   = (const float*)d_in[1];
    const float* mask  = (const float*)d_in[2];
    const float* span  = (const float*)d_in[3];
    float* out = (float*)d_out;

    Ptr6 ws, bs;
    for (int w = 0; w < 6; w++) {
        ws.p[w] = (const float*)d_in[4 + 2 * w];
        bs.p[w] = (const float*)d_in[5 + 2 * w];
    }

    cudaFuncSetAttribute(gemm_mma, cudaFuncAttributeMaxDynamicSharedMemorySize, DYN_SMEM);

    transpose6<<<dim3(Dm / 32, Dm / 32, 6), dim3(32, 8)>>>(ws);
    gemm_mma<<<dim3(Mrows / BM, Dm / BN, 6), 256, DYN_SMEM>>>(query, key, bs);
    zero_loss_kernel<<<1, 1>>>();
    attn_fused<<<dim3(Sq / 16, BHn), 256>>>(mask, span, out);
    finalize_kernel<<<1, 1>>>(out, out_size);
}